// round 4
// baseline (speedup 1.0000x reference)
#include <cuda_runtime.h>

// Output (1,64,64,64,32) fp32 = 2,097,152 float4 total.
// Single-wave persistent shape: 1024 CTAs x 256 threads = 262144 threads,
// each writes exactly 8 float4 at stride 262144 (f4 units).
//
// f4 index f = tid + i*262144 ; position p = f >> 3 ;
//   c = p & 63, r = (p>>6) & 63, z = p >> 12.
// Stride 262144 f4 = 32768 positions = 8 z-groups: the 8 iterations of one
// thread share (r,c) (shared row/col index loads, shared partial address),
// and differ only in z (z0, z0+8, ..., z0+56) -> 8 independent gather loads
// in flight (MLP=8), stores perfectly coalesced per warp.
//
// src scalar = in[ ((z_idx[z]*128 + row_idx[r])*128 + col_idx[c]) * 32 ]

#define K_ILP 8
#define S_F4  262144u   // 2097152 / 8

__global__ __launch_bounds__(256) void sds3d_kernel(
    const float* __restrict__ in,
    const int* __restrict__ z_idx,
    const int* __restrict__ row_idx,
    const int* __restrict__ col_idx,
    float4* __restrict__ out)
{
    unsigned tid = blockIdx.x * 256u + threadIdx.x;   // 0 .. 262143
    unsigned p   = tid >> 3;                          // position 0..32767 (z0 in 0..7)
    unsigned c   = p & 63u;
    unsigned r   = (p >> 6) & 63u;
    unsigned z0  = p >> 12;                           // 0..7

    int ri = __ldg(&row_idx[r]);
    int ci = __ldg(&col_idx[c]);
    unsigned rc = (unsigned)ri * 128u + (unsigned)ci; // shared partial address

    // 8 independent z-index loads
    int zi[K_ILP];
#pragma unroll
    for (int k = 0; k < K_ILP; k++)
        zi[k] = __ldg(&z_idx[z0 + 8u * k]);

    // 8 independent gathers (MLP=8)
    float v[K_ILP];
#pragma unroll
    for (int k = 0; k < K_ILP; k++) {
        unsigned src = ((unsigned)zi[k] * 16384u + rc) * 32u;
        v[k] = __ldg(&in[src]);
    }

    // 8 coalesced 16B stores (plain: let them dirty-hit in L2 across replays)
#pragma unroll
    for (int k = 0; k < K_ILP; k++)
        out[tid + k * S_F4] = make_float4(v[k], v[k], v[k], v[k]);
}

extern "C" void kernel_launch(void* const* d_in, const int* in_sizes, int n_in,
                              void* d_out, int out_size)
{
    const float* in      = (const float*)d_in[0];
    const int*   z_idx   = (const int*)d_in[1];
    const int*   row_idx = (const int*)d_in[2];
    const int*   col_idx = (const int*)d_in[3];
    float4* out = (float4*)d_out;

    sds3d_kernel<<<1024, 256>>>(in, z_idx, row_idx, col_idx, out);
}

// round 5
// speedup vs baseline: 1.0173x; 1.0173x over previous
#include <cuda_runtime.h>
#include <cstdint>

// Output (1,64,64,64,32) fp32 = 2,097,152 float4.
// 2048 CTAs x 128 threads. Each CTA owns a contiguous 16 KB chunk of output
// (1024 float4 = 128 gathered positions x 32 floats).
//
// Phase 1: threads fill the chunk in SMEM. slot = tid + 128*j (j=0..7):
//   consecutive threads -> consecutive float4 slots -> conflict-free STS.128.
//   position p = (chunk_base_f4 + slot) >> 3 ; 8 threads share one position's
//   gathered scalar (same-address LDG -> L1 broadcast). 8 independent gathers
//   per thread in flight (unrolled j loop).
// Phase 2: one thread issues cp.async.bulk (SMEM -> GMEM, 16 KB) — stores go
//   through the bulk/TMA path instead of per-thread STG/L1tex.
//
// src scalar = in[ ((z_idx[z]*128 + row_idx[r])*128 + col_idx[c]) * 32 ]

#define THREADS   128
#define CHUNK_F4  1024              // float4 per CTA = 16 KB

__device__ __forceinline__ uint32_t smem_u32(const void* p) {
    uint32_t a;
    asm("{ .reg .u64 t; cvta.to.shared.u64 t, %1; cvt.u32.u64 %0, t; }"
        : "=r"(a) : "l"(p));
    return a;
}

__global__ __launch_bounds__(THREADS) void sds3d_kernel(
    const float* __restrict__ in,
    const int* __restrict__ z_idx,
    const int* __restrict__ row_idx,
    const int* __restrict__ col_idx,
    float4* __restrict__ out)
{
    __shared__ alignas(128) float4 buf[CHUNK_F4];

    unsigned b    = blockIdx.x;
    unsigned tid  = threadIdx.x;
    unsigned base = b * CHUNK_F4;               // global f4 base of this chunk

#pragma unroll
    for (int j = 0; j < 8; j++) {
        unsigned slot = tid + 128u * j;         // 0..1023
        unsigned p    = (base + slot) >> 3;     // gathered position
        unsigned c    = p & 63u;
        unsigned r    = (p >> 6) & 63u;
        unsigned z    = p >> 12;

        int zi = __ldg(&z_idx[z]);
        int ri = __ldg(&row_idx[r]);
        int ci = __ldg(&col_idx[c]);

        unsigned src = (((unsigned)zi * 128u + (unsigned)ri) * 128u + (unsigned)ci) * 32u;
        float v = __ldg(&in[src]);

        buf[slot] = make_float4(v, v, v, v);
    }

    __syncthreads();
    asm volatile("fence.proxy.async.shared::cta;" ::: "memory");

    if (tid == 0) {
        uint32_t s = smem_u32(buf);
        asm volatile(
            "cp.async.bulk.global.shared::cta.bulk_group [%0], [%1], %2;\n\t"
            "cp.async.bulk.commit_group;\n\t"
            :: "l"(out + base), "r"(s), "r"((unsigned)(CHUNK_F4 * 16))
            : "memory");
        asm volatile("cp.async.bulk.wait_group 0;" ::: "memory");
    }
}

extern "C" void kernel_launch(void* const* d_in, const int* in_sizes, int n_in,
                              void* d_out, int out_size)
{
    const float* in      = (const float*)d_in[0];
    const int*   z_idx   = (const int*)d_in[1];
    const int*   row_idx = (const int*)d_in[2];
    const int*   col_idx = (const int*)d_in[3];
    float4* out = (float4*)d_out;

    sds3d_kernel<<<2097152 / CHUNK_F4, THREADS>>>(in, z_idx, row_idx, col_idx, out);
}